// round 1
// baseline (speedup 1.0000x reference)
#include <cuda_runtime.h>
#include <math.h>

// Problem constants (fixed shapes from reference)
#define T_DIM 2048
#define B_DIM 16
#define D_DIM 1024
#define M_DIM (T_DIM * B_DIM)       // 32768 rows for the GEMMs
#define BD    (B_DIM * D_DIM)       // 16384 parallel scan chains

// Scratch for k_all / v_all (device globals: allocation-guard legal)
__device__ float g_k[(size_t)M_DIM * D_DIM];   // 128 MB
__device__ float g_v[(size_t)M_DIM * D_DIM];   // 128 MB

__device__ __forceinline__ float fast_sigmoid(float x) {
    return 1.0f / (1.0f + __expf(-x));
}

// ----------------------------------------------------------------------------
// Fused NT-GEMM + bias + activation.
//   C[m,n] = act( sum_d A[m,d] * W[n,d] + bias[n] )
// A: [M, K] row-major (x flattened [T*B, D]), W: [N, K] row-major.
// ACT == 0 -> sigmoid -> g_k ;  ACT == 1 -> tanh -> g_v
// Tiling: 128x128x8, 256 threads, 8x8 per-thread microtile.
// ----------------------------------------------------------------------------
template <int ACT>
__global__ __launch_bounds__(256, 2)
void gemm_act_kernel(const float* __restrict__ A,
                     const float* __restrict__ W,
                     const float* __restrict__ bias)
{
    constexpr int BM = 128, BN = 128, BK = 8;
    __shared__ float As[BK][BM];
    __shared__ float Bs[BK][BN];

    float* __restrict__ C = (ACT == 0) ? g_k : g_v;

    const int bm  = blockIdx.y * BM;
    const int bn  = blockIdx.x * BN;
    const int tid = threadIdx.x;

    // gmem->smem load mapping: 256 threads x float4 covers 128x8 tile
    const int lrow = tid >> 1;            // 0..127
    const int lcol = (tid & 1) * 4;       // 0 or 4

    // compute mapping: 16x16 thread grid, 8x8 microtile each
    const int ty = tid >> 4;              // 0..15
    const int tx = tid & 15;              // 0..15

    const float* Aptr = A + (size_t)(bm + lrow) * D_DIM + lcol;
    const float* Wptr = W + (size_t)(bn + lrow) * D_DIM + lcol;

    float acc[8][8];
#pragma unroll
    for (int i = 0; i < 8; i++)
#pragma unroll
        for (int j = 0; j < 8; j++)
            acc[i][j] = 0.0f;

    for (int k0 = 0; k0 < D_DIM; k0 += BK) {
        float4 av = *(const float4*)(Aptr + k0);
        float4 bv = *(const float4*)(Wptr + k0);
        As[lcol + 0][lrow] = av.x;
        As[lcol + 1][lrow] = av.y;
        As[lcol + 2][lrow] = av.z;
        As[lcol + 3][lrow] = av.w;
        Bs[lcol + 0][lrow] = bv.x;
        Bs[lcol + 1][lrow] = bv.y;
        Bs[lcol + 2][lrow] = bv.z;
        Bs[lcol + 3][lrow] = bv.w;
        __syncthreads();

#pragma unroll
        for (int kk = 0; kk < BK; kk++) {
            float a[8], b[8];
            *(float4*)&a[0] = *(const float4*)&As[kk][ty * 8 + 0];
            *(float4*)&a[4] = *(const float4*)&As[kk][ty * 8 + 4];
            *(float4*)&b[0] = *(const float4*)&Bs[kk][tx * 8 + 0];
            *(float4*)&b[4] = *(const float4*)&Bs[kk][tx * 8 + 4];
#pragma unroll
            for (int i = 0; i < 8; i++)
#pragma unroll
                for (int j = 0; j < 8; j++)
                    acc[i][j] = fmaf(a[i], b[j], acc[i][j]);
        }
        __syncthreads();
    }

    // Epilogue: bias + activation, vectorized stores (n-contiguous)
    float bcol[8];
#pragma unroll
    for (int j = 0; j < 8; j++)
        bcol[j] = bias[bn + tx * 8 + j];

#pragma unroll
    for (int i = 0; i < 8; i++) {
        float r[8];
#pragma unroll
        for (int j = 0; j < 8; j++) {
            float v = acc[i][j] + bcol[j];
            r[j] = (ACT == 0) ? fast_sigmoid(v) : tanhf(v);
        }
        float* crow = C + (size_t)(bm + ty * 8 + i) * D_DIM + bn + tx * 8;
        *(float4*)&crow[0] = *(const float4*)&r[0];
        *(float4*)&crow[4] = *(const float4*)&r[4];
    }
}

// ----------------------------------------------------------------------------
// Sequential scan over T, parallel over B*D chains.
//   h_t = (1-k_t)*h_{t-1} + k_t*v_t
//   out_o[t] = h_t^2 * sigmoid(h_t)   (h * silu(h))
//   out_h[0] = h0 ; out_h[t+1] = h_t
// ----------------------------------------------------------------------------
__global__ __launch_bounds__(128)
void scan_kernel(const float* __restrict__ h0,
                 float* __restrict__ out_o,
                 float* __restrict__ out_h)
{
    const int i = blockIdx.x * blockDim.x + threadIdx.x;  // 0..BD-1
    float h = h0[i];
    out_h[i] = h;

    const float* __restrict__ kp = g_k + i;
    const float* __restrict__ vp = g_v + i;
    float* __restrict__ op = out_o + i;
    float* __restrict__ hp = out_h + BD + i;

#pragma unroll 4
    for (int t = 0; t < T_DIM; t++) {
        float k = kp[(size_t)t * BD];
        float v = vp[(size_t)t * BD];
        h = (1.0f - k) * h + k * v;
        hp[(size_t)t * BD] = h;
        float s = fast_sigmoid(h);
        op[(size_t)t * BD] = h * h * s;
    }
}

// ----------------------------------------------------------------------------
// kernel_launch: inputs per metadata order:
//   0: x [T,B,D]  1: h0 [B,D]  2: W_k [D,D]  3: b_k [D]  4: W_v [D,D]  5: b_v [D]
// d_out: output [T,B,D] followed by h [T+1,B,D]  (tuple flattening order)
// ----------------------------------------------------------------------------
extern "C" void kernel_launch(void* const* d_in, const int* in_sizes, int n_in,
                              void* d_out, int out_size)
{
    const float* x   = (const float*)d_in[0];
    const float* h0  = (const float*)d_in[1];
    const float* W_k = (const float*)d_in[2];
    const float* b_k = (const float*)d_in[3];
    const float* W_v = (const float*)d_in[4];
    const float* b_v = (const float*)d_in[5];

    float* out   = (float*)d_out;
    float* out_o = out;                              // [T, B, D]
    float* out_h = out + (size_t)T_DIM * BD;         // [T+1, B, D]

    dim3 ggrid(D_DIM / 128, M_DIM / 128);            // (8, 256)
    gemm_act_kernel<0><<<ggrid, 256>>>(x, W_k, b_k); // k_all = sigmoid(...)
    gemm_act_kernel<1><<<ggrid, 256>>>(x, W_v, b_v); // v_all = tanh(...)

    scan_kernel<<<BD / 128, 128>>>(h0, out_o, out_h);
}

// round 3
// speedup vs baseline: 2.4175x; 2.4175x over previous
#include <cuda_runtime.h>
#include <cuda_bf16.h>
#include <math.h>
#include <stdint.h>

// ---------------------------------------------------------------- constants
#define T_DIM 2048
#define B_DIM 16
#define D_DIM 1024
#define M_DIM (T_DIM * B_DIM)     // 32768
#define BD    (B_DIM * D_DIM)     // 16384

// ---------------------------------------------------------------- scratch
__device__ float g_k[(size_t)M_DIM * D_DIM];              // sigmoid gate
__device__ float g_v[(size_t)M_DIM * D_DIM];              // tanh value
__device__ __nv_bfloat16 g_xh[(size_t)M_DIM * D_DIM];     // x hi plane
__device__ __nv_bfloat16 g_xl[(size_t)M_DIM * D_DIM];     // x lo plane
__device__ __nv_bfloat16 g_wkh[(size_t)D_DIM * D_DIM];
__device__ __nv_bfloat16 g_wkl[(size_t)D_DIM * D_DIM];
__device__ __nv_bfloat16 g_wvh[(size_t)D_DIM * D_DIM];
__device__ __nv_bfloat16 g_wvl[(size_t)D_DIM * D_DIM];

__device__ __forceinline__ float fast_sigmoid(float x) {
    return 1.0f / (1.0f + __expf(-x));
}

__device__ __forceinline__ uint32_t smem_u32(const void* p) {
    uint32_t a;
    asm("{ .reg .u64 t; cvta.to.shared.u64 t, %1; cvt.u32.u64 %0, t; }"
        : "=r"(a) : "l"(p));
    return a;
}

// ---------------------------------------------------------------- split
// f32 -> bf16 hi + bf16 lo (f ~= hi + lo). float4 per thread.
__global__ __launch_bounds__(256)
void split_kernel(const float* __restrict__ src,
                  __nv_bfloat16* __restrict__ hi,
                  __nv_bfloat16* __restrict__ lo, int n4)
{
    int i = blockIdx.x * 256 + threadIdx.x;
    if (i >= n4) return;
    float4 f = ((const float4*)src)[i];
    union { __nv_bfloat16 h[4]; unsigned long long u; } H, L;
    H.h[0] = __float2bfloat16(f.x);
    H.h[1] = __float2bfloat16(f.y);
    H.h[2] = __float2bfloat16(f.z);
    H.h[3] = __float2bfloat16(f.w);
    L.h[0] = __float2bfloat16(f.x - __bfloat162float(H.h[0]));
    L.h[1] = __float2bfloat16(f.y - __bfloat162float(H.h[1]));
    L.h[2] = __float2bfloat16(f.z - __bfloat162float(H.h[2]));
    L.h[3] = __float2bfloat16(f.w - __bfloat162float(H.h[3]));
    ((unsigned long long*)hi)[i] = H.u;
    ((unsigned long long*)lo)[i] = L.u;
}

// ---------------------------------------------------------------- fused GEMM
// One CTA: 128x128 tile of BOTH k and v. K' = 3*1024 split schedule:
//   p0: Ah*Wh   p1: Ah*Wl   p2: Al*Wh
// 512 threads = 16 warps in 4(m) x 4(n); warp tile 32x32 per output.
static constexpr int BM = 128, BN = 128, KCH = 32;   // KCH bf16 per chunk
static constexpr int NCH = 3 * D_DIM / KCH;          // 96 chunks
static constexpr int ROWB = KCH * 2 + 16;            // 80 B padded row
static constexpr int A_ST = BM * ROWB;               // 10240 B per tile
static constexpr int STAGE = 3 * A_ST;               // A, Wk, Wv
static constexpr int NSTG = 4;
static constexpr int SMEM_SZ = NSTG * STAGE;         // 122880 B

#define CP_ASYNC16(dst, src) \
    asm volatile("cp.async.cg.shared.global [%0], [%1], 16;" :: "r"(dst), "l"(src))
#define CP_COMMIT() asm volatile("cp.async.commit_group;" ::: "memory")
#define CP_WAIT3()  asm volatile("cp.async.wait_group 3;" ::: "memory")

#define LDSM_X4(r0, r1, r2, r3, addr) \
    asm volatile("ldmatrix.sync.aligned.m8n8.x4.shared.b16 {%0,%1,%2,%3}, [%4];" \
                 : "=r"(r0), "=r"(r1), "=r"(r2), "=r"(r3) : "r"(addr))

#define MMA_BF16(d, a, b) \
    asm volatile("mma.sync.aligned.m16n8k16.row.col.f32.bf16.bf16.f32 " \
                 "{%0,%1,%2,%3}, {%4,%5,%6,%7}, {%8,%9}, {%0,%1,%2,%3};" \
                 : "+f"((d)[0]), "+f"((d)[1]), "+f"((d)[2]), "+f"((d)[3]) \
                 : "r"((a)[0]), "r"((a)[1]), "r"((a)[2]), "r"((a)[3]),   \
                   "r"((b)[0]), "r"((b)[1]))

__global__ __launch_bounds__(512, 1)
void fused_gemm_kv(const float* __restrict__ bk, const float* __restrict__ bv)
{
    extern __shared__ char smem[];
    const uint32_t sb = smem_u32(smem);
    const int tid = threadIdx.x;
    const int wid = tid >> 5;
    const int lid = tid & 31;
    const int bm = blockIdx.y * BM;
    const int bn = blockIdx.x * BN;

    const int wm0 = (wid & 3) * 32;    // warp m offset within tile
    const int wn0 = (wid >> 2) * 32;   // warp n offset within tile

    // cp.async mapping: one 16B chunk per thread per tile
    const int lrow = tid >> 2;         // 0..127
    const int lc16 = tid & 3;          // 16B column chunk

    float acc[2][2][4][4];             // [out][mfrag][nfrag][4]
    #pragma unroll
    for (int o = 0; o < 2; ++o)
        #pragma unroll
        for (int i = 0; i < 2; ++i)
            #pragma unroll
            for (int j = 0; j < 4; ++j)
                #pragma unroll
                for (int r = 0; r < 4; ++r) acc[o][i][j][r] = 0.0f;

    auto issue_load = [&](int chunk, int buf) {
        const int p  = chunk >> 5;                 // plane pair 0..2
        const int kk = (chunk & 31) * KCH;         // bf16 k offset
        const __nv_bfloat16* Ap = (p == 2) ? g_xl : g_xh;
        const __nv_bfloat16* Kp = (p == 1) ? g_wkl : g_wkh;
        const __nv_bfloat16* Vp = (p == 1) ? g_wvl : g_wvh;
        const uint32_t d0 = sb + buf * STAGE + lrow * ROWB + lc16 * 16;
        const __nv_bfloat16* sA = Ap + (size_t)(bm + lrow) * D_DIM + kk + lc16 * 8;
        const __nv_bfloat16* sK = Kp + (size_t)(bn + lrow) * D_DIM + kk + lc16 * 8;
        const __nv_bfloat16* sV = Vp + (size_t)(bn + lrow) * D_DIM + kk + lc16 * 8;
        CP_ASYNC16(d0,            sA);
        CP_ASYNC16(d0 + A_ST,     sK);
        CP_ASYNC16(d0 + 2 * A_ST, sV);
    };

    // prologue: stages 0..2
    #pragma unroll
    for (int s = 0; s < 3; ++s) { issue_load(s, s); CP_COMMIT(); }

    for (int c = 0; c < NCH; ++c) {
        if (c + 3 < NCH) issue_load(c + 3, (c + 3) & 3);
        CP_COMMIT();
        CP_WAIT3();
        __syncthreads();

        const uint32_t Ab = sb + (c & 3) * STAGE;
        #pragma unroll
        for (int s = 0; s < 2; ++s) {              // two k16 steps
            uint32_t a[2][4];
            #pragma unroll
            for (int mf = 0; mf < 2; ++mf) {
                uint32_t addr = Ab + (uint32_t)(wm0 + mf * 16 + (lid & 15)) * ROWB
                              + s * 32 + (lid >> 4) * 16;
                LDSM_X4(a[mf][0], a[mf][1], a[mf][2], a[mf][3], addr);
            }
            uint32_t b[2][4][2];
            #pragma unroll
            for (int o = 0; o < 2; ++o) {
                const uint32_t Bb = Ab + (1 + o) * A_ST;
                #pragma unroll
                for (int nf2 = 0; nf2 < 2; ++nf2) {
                    uint32_t addr = Bb
                        + (uint32_t)(wn0 + nf2 * 16 + (lid & 7) + ((lid >> 4) & 1) * 8) * ROWB
                        + s * 32 + ((lid >> 3) & 1) * 16;
                    LDSM_X4(b[o][nf2 * 2][0], b[o][nf2 * 2][1],
                            b[o][nf2 * 2 + 1][0], b[o][nf2 * 2 + 1][1], addr);
                }
            }
            #pragma unroll
            for (int o = 0; o < 2; ++o)
                #pragma unroll
                for (int mf = 0; mf < 2; ++mf)
                    #pragma unroll
                    for (int nf = 0; nf < 4; ++nf)
                        MMA_BF16(acc[o][mf][nf], a[mf], b[o][nf]);
        }
        __syncthreads();
    }

    // epilogue: bias + activation, direct f32x2 stores
    const int grow = lid >> 2;
    const int gcol = (lid & 3) * 2;
    #pragma unroll
    for (int o = 0; o < 2; ++o) {
        float* dst = o ? g_v : g_k;
        const float* bias = o ? bv : bk;
        #pragma unroll
        for (int nf = 0; nf < 4; ++nf) {
            const int col = bn + wn0 + nf * 8 + gcol;
            const float b0 = bias[col], b1 = bias[col + 1];
            #pragma unroll
            for (int mf = 0; mf < 2; ++mf) {
                const int r0 = bm + wm0 + mf * 16 + grow;
                float z0 = acc[o][mf][nf][0] + b0;
                float z1 = acc[o][mf][nf][1] + b1;
                float z2 = acc[o][mf][nf][2] + b0;
                float z3 = acc[o][mf][nf][3] + b1;
                float2 lo_, hi_;
                if (o == 0) {
                    lo_ = make_float2(fast_sigmoid(z0), fast_sigmoid(z1));
                    hi_ = make_float2(fast_sigmoid(z2), fast_sigmoid(z3));
                } else {
                    lo_ = make_float2(tanhf(z0), tanhf(z1));
                    hi_ = make_float2(tanhf(z2), tanhf(z3));
                }
                *(float2*)(dst + (size_t)r0 * D_DIM + col)       = lo_;
                *(float2*)(dst + (size_t)(r0 + 8) * D_DIM + col) = hi_;
            }
        }
    }
}

// ---------------------------------------------------------------- scan
__global__ __launch_bounds__(128)
void scan_kernel(const float* __restrict__ h0,
                 float* __restrict__ out_o,
                 float* __restrict__ out_h)
{
    const int i = blockIdx.x * 128 + threadIdx.x;
    float h = h0[i];
    out_h[i] = h;

    const float* __restrict__ kp = g_k + i;
    const float* __restrict__ vp = g_v + i;
    float* __restrict__ op = out_o + i;
    float* __restrict__ hp = out_h + BD + i;

    constexpr int U = 8;
    float ka[U], va[U], kb[U], vb[U];
    #pragma unroll
    for (int u = 0; u < U; ++u) {
        ka[u] = kp[(size_t)u * BD];
        va[u] = vp[(size_t)u * BD];
    }

    for (int t0 = 0; t0 < T_DIM; t0 += U) {
        if (t0 + U < T_DIM) {
            #pragma unroll
            for (int u = 0; u < U; ++u) {
                kb[u] = kp[(size_t)(t0 + U + u) * BD];
                vb[u] = vp[(size_t)(t0 + U + u) * BD];
            }
        }
        #pragma unroll
        for (int u = 0; u < U; ++u) {
            h = (1.0f - ka[u]) * h + ka[u] * va[u];
            hp[(size_t)(t0 + u) * BD] = h;
            float s = fast_sigmoid(h);
            op[(size_t)(t0 + u) * BD] = h * h * s;
        }
        #pragma unroll
        for (int u = 0; u < U; ++u) { ka[u] = kb[u]; va[u] = vb[u]; }
    }
}

// ---------------------------------------------------------------- launch
extern "C" void kernel_launch(void* const* d_in, const int* in_sizes, int n_in,
                              void* d_out, int out_size)
{
    const float* x   = (const float*)d_in[0];
    const float* h0  = (const float*)d_in[1];
    const float* W_k = (const float*)d_in[2];
    const float* b_k = (const float*)d_in[3];
    const float* W_v = (const float*)d_in[4];
    const float* b_v = (const float*)d_in[5];

    float* out   = (float*)d_out;
    float* out_o = out;                           // [T, B, D]
    float* out_h = out + (size_t)T_DIM * BD;      // [T+1, B, D]

    // resolve device-global scratch addresses
    __nv_bfloat16 *xh, *xl, *wkh, *wkl, *wvh, *wvl;
    cudaGetSymbolAddress((void**)&xh,  g_xh);
    cudaGetSymbolAddress((void**)&xl,  g_xl);
    cudaGetSymbolAddress((void**)&wkh, g_wkh);
    cudaGetSymbolAddress((void**)&wkl, g_wkl);
    cudaGetSymbolAddress((void**)&wvh, g_wvh);
    cudaGetSymbolAddress((void**)&wvl, g_wvl);

    // split fp32 -> bf16 hi/lo planes
    const int n4x = (M_DIM * D_DIM) / 4;          // 8388608
    const int n4w = (D_DIM * D_DIM) / 4;          // 262144
    split_kernel<<<(n4x + 255) / 256, 256>>>(x,   xh,  xl,  n4x);
    split_kernel<<<(n4w + 255) / 256, 256>>>(W_k, wkh, wkl, n4w);
    split_kernel<<<(n4w + 255) / 256, 256>>>(W_v, wvh, wvl, n4w);

    cudaFuncSetAttribute(fused_gemm_kv,
                         cudaFuncAttributeMaxDynamicSharedMemorySize, SMEM_SZ);
    dim3 grid(D_DIM / BN, M_DIM / BM);            // (8, 256)
    fused_gemm_kv<<<grid, 512, SMEM_SZ>>>(b_k, b_v);

    scan_kernel<<<BD / 128, 128>>>(h0, out_o, out_h);
}

// round 4
// speedup vs baseline: 3.2162x; 1.3304x over previous
#include <cuda_runtime.h>
#include <cuda_bf16.h>
#include <math.h>
#include <stdint.h>

// ---------------------------------------------------------------- constants
#define T_DIM 2048
#define B_DIM 16
#define D_DIM 1024
#define M_DIM (T_DIM * B_DIM)     // 32768
#define BD    (B_DIM * D_DIM)     // 16384
#define NSEG  16
#define SEGT  (T_DIM / NSEG)      // 128

// ---------------------------------------------------------------- scratch
__device__ float g_k[(size_t)M_DIM * D_DIM];              // sigmoid gate
__device__ float g_v[(size_t)M_DIM * D_DIM];              // tanh value
__device__ __nv_bfloat16 g_xh[(size_t)M_DIM * D_DIM];
__device__ __nv_bfloat16 g_xl[(size_t)M_DIM * D_DIM];
__device__ __nv_bfloat16 g_wkh[(size_t)D_DIM * D_DIM];
__device__ __nv_bfloat16 g_wkl[(size_t)D_DIM * D_DIM];
__device__ __nv_bfloat16 g_wvh[(size_t)D_DIM * D_DIM];
__device__ __nv_bfloat16 g_wvl[(size_t)D_DIM * D_DIM];
__device__ float g_segA[NSEG * BD];
__device__ float g_segB[NSEG * BD];
__device__ float g_hstart[NSEG * BD];

__device__ __forceinline__ float fast_sigmoid(float x) {
    return 1.0f / (1.0f + __expf(-x));
}

__device__ __forceinline__ uint32_t smem_u32(const void* p) {
    uint32_t a;
    asm("{ .reg .u64 t; cvta.to.shared.u64 t, %1; cvt.u32.u64 %0, t; }"
        : "=r"(a) : "l"(p));
    return a;
}

// ---------------------------------------------------------------- split
__global__ __launch_bounds__(256)
void split_kernel(const float* __restrict__ src,
                  __nv_bfloat16* __restrict__ hi,
                  __nv_bfloat16* __restrict__ lo, int n4)
{
    int i = blockIdx.x * 256 + threadIdx.x;
    if (i >= n4) return;
    float4 f = ((const float4*)src)[i];
    union { __nv_bfloat16 h[4]; unsigned long long u; } H, L;
    H.h[0] = __float2bfloat16(f.x);
    H.h[1] = __float2bfloat16(f.y);
    H.h[2] = __float2bfloat16(f.z);
    H.h[3] = __float2bfloat16(f.w);
    L.h[0] = __float2bfloat16(f.x - __bfloat162float(H.h[0]));
    L.h[1] = __float2bfloat16(f.y - __bfloat162float(H.h[1]));
    L.h[2] = __float2bfloat16(f.z - __bfloat162float(H.h[2]));
    L.h[3] = __float2bfloat16(f.w - __bfloat162float(H.h[3]));
    ((unsigned long long*)hi)[i] = H.u;
    ((unsigned long long*)lo)[i] = L.u;
}

// ---------------------------------------------------------------- fused GEMM
// One CTA: 128x128 tile of BOTH k and v. K' = 3*1024 split schedule:
//   p0: Ah*Wh   p1: Ah*Wl   p2: Al*Wh
// 512 threads = 16 warps in 4(m) x 4(n); warp tile 32x32 per output.
// 64-wide K chunks, 3-stage cp.async pipeline, ONE __syncthreads per chunk.
static constexpr int BM = 128, BN = 128, KCH = 64;
static constexpr int NCH = 3 * D_DIM / KCH;          // 48 chunks
static constexpr int ROWB = KCH * 2 + 16;            // 144 B padded row
static constexpr int A_ST = BM * ROWB;               // 18432 B per tile
static constexpr int STAGE = 3 * A_ST;               // 55296 B (A, Wk, Wv)
static constexpr int NSTG = 3;
static constexpr int SMEM_SZ = NSTG * STAGE;         // 165888 B

#define CP_ASYNC16(dst, src) \
    asm volatile("cp.async.cg.shared.global [%0], [%1], 16;" :: "r"(dst), "l"(src))
#define CP_COMMIT() asm volatile("cp.async.commit_group;" ::: "memory")
#define CP_WAIT1()  asm volatile("cp.async.wait_group 1;" ::: "memory")

#define LDSM_X4(r0, r1, r2, r3, addr) \
    asm volatile("ldmatrix.sync.aligned.m8n8.x4.shared.b16 {%0,%1,%2,%3}, [%4];" \
                 : "=r"(r0), "=r"(r1), "=r"(r2), "=r"(r3) : "r"(addr))

#define MMA_BF16(d, a, b) \
    asm volatile("mma.sync.aligned.m16n8k16.row.col.f32.bf16.bf16.f32 " \
                 "{%0,%1,%2,%3}, {%4,%5,%6,%7}, {%8,%9}, {%0,%1,%2,%3};" \
                 : "+f"((d)[0]), "+f"((d)[1]), "+f"((d)[2]), "+f"((d)[3]) \
                 : "r"((a)[0]), "r"((a)[1]), "r"((a)[2]), "r"((a)[3]),   \
                   "r"((b)[0]), "r"((b)[1]))

__global__ __launch_bounds__(512, 1)
void fused_gemm_kv(const float* __restrict__ bk, const float* __restrict__ bv)
{
    extern __shared__ char smem[];
    const uint32_t sb = smem_u32(smem);
    const int tid = threadIdx.x;
    const int wid = tid >> 5;
    const int lid = tid & 31;
    const int bm = blockIdx.y * BM;
    const int bn = blockIdx.x * BN;

    const int wm0 = (wid & 3) * 32;
    const int wn0 = (wid >> 2) * 32;

    // cp.async mapping: 128 rows x 128 B = 1024 x 16B chunks; 2 per thread
    const int lrow0 = tid >> 3;          // rows 0..63  (t=0)
    const int lc16  = tid & 7;           // 16B column chunk 0..7

    float acc[2][2][4][4];
    #pragma unroll
    for (int o = 0; o < 2; ++o)
        #pragma unroll
        for (int i = 0; i < 2; ++i)
            #pragma unroll
            for (int j = 0; j < 4; ++j)
                #pragma unroll
                for (int r = 0; r < 4; ++r) acc[o][i][j][r] = 0.0f;

    auto issue_load = [&](int chunk, int buf) {
        const int p  = chunk >> 4;                 // plane pair 0..2 (16 chunks each)
        const int kk = (chunk & 15) * KCH;
        const __nv_bfloat16* Ap = (p == 2) ? g_xl : g_xh;
        const __nv_bfloat16* Kp = (p == 1) ? g_wkl : g_wkh;
        const __nv_bfloat16* Vp = (p == 1) ? g_wvl : g_wvh;
        #pragma unroll
        for (int t = 0; t < 2; ++t) {
            const int r = lrow0 + t * 64;
            const uint32_t d0 = sb + buf * STAGE + r * ROWB + lc16 * 16;
            CP_ASYNC16(d0,            Ap + (size_t)(bm + r) * D_DIM + kk + lc16 * 8);
            CP_ASYNC16(d0 + A_ST,     Kp + (size_t)(bn + r) * D_DIM + kk + lc16 * 8);
            CP_ASYNC16(d0 + 2 * A_ST, Vp + (size_t)(bn + r) * D_DIM + kk + lc16 * 8);
        }
    };

    issue_load(0, 0); CP_COMMIT();
    issue_load(1, 1); CP_COMMIT();

    int buf_c = 0, buf_n = 2;   // buffer of chunk c ; buffer to fill next
    for (int c = 0; c < NCH; ++c) {
        CP_WAIT1();
        __syncthreads();
        // safe: buffer buf_n == (c-1)%3 finished being read before the barrier
        if (c + 2 < NCH) issue_load(c + 2, buf_n);
        CP_COMMIT();

        const uint32_t Ab = sb + buf_c * STAGE;
        buf_n = buf_c;
        buf_c = (buf_c + 1 == 3) ? 0 : buf_c + 1;

        #pragma unroll
        for (int s = 0; s < 4; ++s) {              // four k16 steps
            uint32_t a[2][4];
            #pragma unroll
            for (int mf = 0; mf < 2; ++mf) {
                uint32_t addr = Ab + (uint32_t)(wm0 + mf * 16 + (lid & 15)) * ROWB
                              + s * 32 + (lid >> 4) * 16;
                LDSM_X4(a[mf][0], a[mf][1], a[mf][2], a[mf][3], addr);
            }
            uint32_t b[2][4][2];
            #pragma unroll
            for (int o = 0; o < 2; ++o) {
                const uint32_t Bb = Ab + (1 + o) * A_ST;
                #pragma unroll
                for (int nf2 = 0; nf2 < 2; ++nf2) {
                    uint32_t addr = Bb
                        + (uint32_t)(wn0 + nf2 * 16 + (lid & 7) + ((lid >> 4) & 1) * 8) * ROWB
                        + s * 32 + ((lid >> 3) & 1) * 16;
                    LDSM_X4(b[o][nf2 * 2][0], b[o][nf2 * 2][1],
                            b[o][nf2 * 2 + 1][0], b[o][nf2 * 2 + 1][1], addr);
                }
            }
            #pragma unroll
            for (int o = 0; o < 2; ++o)
                #pragma unroll
                for (int mf = 0; mf < 2; ++mf)
                    #pragma unroll
                    for (int nf = 0; nf < 4; ++nf)
                        MMA_BF16(acc[o][mf][nf], a[mf], b[o][nf]);
        }
    }

    // epilogue: bias + activation, f32x2 stores
    const int grow = lid >> 2;
    const int gcol = (lid & 3) * 2;
    #pragma unroll
    for (int o = 0; o < 2; ++o) {
        float* dst = o ? g_v : g_k;
        const float* bias = o ? bv : bk;
        #pragma unroll
        for (int nf = 0; nf < 4; ++nf) {
            const int col = bn + wn0 + nf * 8 + gcol;
            const float b0 = bias[col], b1 = bias[col + 1];
            #pragma unroll
            for (int mf = 0; mf < 2; ++mf) {
                const int r0 = bm + wm0 + mf * 16 + grow;
                float z0 = acc[o][mf][nf][0] + b0;
                float z1 = acc[o][mf][nf][1] + b1;
                float z2 = acc[o][mf][nf][2] + b0;
                float z3 = acc[o][mf][nf][3] + b1;
                float2 lo_, hi_;
                if (o == 0) {
                    lo_ = make_float2(fast_sigmoid(z0), fast_sigmoid(z1));
                    hi_ = make_float2(fast_sigmoid(z2), fast_sigmoid(z3));
                } else {
                    lo_ = make_float2(tanhf(z0), tanhf(z1));
                    hi_ = make_float2(tanhf(z2), tanhf(z3));
                }
                *(float2*)(dst + (size_t)r0 * D_DIM + col)       = lo_;
                *(float2*)(dst + (size_t)(r0 + 8) * D_DIM + col) = hi_;
            }
        }
    }
}

// ---------------------------------------------------------------- seg scan
// Phase A: per (chain, segment) compose h_out = A*h_in + B over SEGT steps.
__global__ __launch_bounds__(256)
void scanA_kernel()
{
    const int idx = blockIdx.x * 256 + threadIdx.x;   // 0..NSEG*BD-1
    const int i = idx & (BD - 1);
    const int s = idx >> 14;                          // BD = 2^14
    const size_t base = (size_t)(s * SEGT) * BD + i;

    const float* __restrict__ kp = g_k + base;
    const float* __restrict__ vp = g_v + base;

    float A = 1.0f, B = 0.0f;
    constexpr int U = 8;
    float ka[U], va[U], kb[U], vb[U];
    #pragma unroll
    for (int u = 0; u < U; ++u) { ka[u] = kp[(size_t)u * BD]; va[u] = vp[(size_t)u * BD]; }

    for (int j0 = 0; j0 < SEGT; j0 += U) {
        if (j0 + U < SEGT) {
            #pragma unroll
            for (int u = 0; u < U; ++u) {
                kb[u] = kp[(size_t)(j0 + U + u) * BD];
                vb[u] = vp[(size_t)(j0 + U + u) * BD];
            }
        }
        #pragma unroll
        for (int u = 0; u < U; ++u) {
            const float om = 1.0f - ka[u];
            B = om * B + ka[u] * va[u];
            A = om * A;
        }
        #pragma unroll
        for (int u = 0; u < U; ++u) { ka[u] = kb[u]; va[u] = vb[u]; }
    }
    g_segA[idx] = A;
    g_segB[idx] = B;
}

// Phase B: per chain, prefix over the NSEG segments; also write out_h[0].
__global__ __launch_bounds__(128)
void scanB_kernel(const float* __restrict__ h0, float* __restrict__ out_h)
{
    const int i = blockIdx.x * 128 + threadIdx.x;
    float h = h0[i];
    out_h[i] = h;
    #pragma unroll
    for (int s = 0; s < NSEG; ++s) {
        g_hstart[s * BD + i] = h;
        h = g_segA[s * BD + i] * h + g_segB[s * BD + i];
    }
}

// Phase C: replay each segment from h_start, write out_h / out_o.
__global__ __launch_bounds__(256)
void scanC_kernel(float* __restrict__ out_o, float* __restrict__ out_h)
{
    const int idx = blockIdx.x * 256 + threadIdx.x;
    const int i = idx & (BD - 1);
    const int s = idx >> 14;
    const int t0 = s * SEGT;
    const size_t base = (size_t)t0 * BD + i;

    const float* __restrict__ kp = g_k + base;
    const float* __restrict__ vp = g_v + base;
    float* __restrict__ op = out_o + base;
    float* __restrict__ hp = out_h + (size_t)BD + base;

    float h = g_hstart[s * BD + i];
    constexpr int U = 8;
    float ka[U], va[U], kb[U], vb[U];
    #pragma unroll
    for (int u = 0; u < U; ++u) { ka[u] = kp[(size_t)u * BD]; va[u] = vp[(size_t)u * BD]; }

    for (int j0 = 0; j0 < SEGT; j0 += U) {
        if (j0 + U < SEGT) {
            #pragma unroll
            for (int u = 0; u < U; ++u) {
                kb[u] = kp[(size_t)(j0 + U + u) * BD];
                vb[u] = vp[(size_t)(j0 + U + u) * BD];
            }
        }
        #pragma unroll
        for (int u = 0; u < U; ++u) {
            h = (1.0f - ka[u]) * h + ka[u] * va[u];
            hp[(size_t)(j0 + u) * BD] = h;
            float sg = fast_sigmoid(h);
            op[(size_t)(j0 + u) * BD] = h * h * sg;
        }
        #pragma unroll
        for (int u = 0; u < U; ++u) { ka[u] = kb[u]; va[u] = vb[u]; }
    }
}

// ---------------------------------------------------------------- launch
extern "C" void kernel_launch(void* const* d_in, const int* in_sizes, int n_in,
                              void* d_out, int out_size)
{
    const float* x   = (const float*)d_in[0];
    const float* h0  = (const float*)d_in[1];
    const float* W_k = (const float*)d_in[2];
    const float* b_k = (const float*)d_in[3];
    const float* W_v = (const float*)d_in[4];
    const float* b_v = (const float*)d_in[5];

    float* out   = (float*)d_out;
    float* out_o = out;                           // [T, B, D]
    float* out_h = out + (size_t)T_DIM * BD;      // [T+1, B, D]

    __nv_bfloat16 *xh, *xl, *wkh, *wkl, *wvh, *wvl;
    cudaGetSymbolAddress((void**)&xh,  g_xh);
    cudaGetSymbolAddress((void**)&xl,  g_xl);
    cudaGetSymbolAddress((void**)&wkh, g_wkh);
    cudaGetSymbolAddress((void**)&wkl, g_wkl);
    cudaGetSymbolAddress((void**)&wvh, g_wvh);
    cudaGetSymbolAddress((void**)&wvl, g_wvl);

    const int n4x = (M_DIM * D_DIM) / 4;
    const int n4w = (D_DIM * D_DIM) / 4;
    split_kernel<<<(n4x + 255) / 256, 256>>>(x,   xh,  xl,  n4x);
    split_kernel<<<(n4w + 255) / 256, 256>>>(W_k, wkh, wkl, n4w);
    split_kernel<<<(n4w + 255) / 256, 256>>>(W_v, wvh, wvl, n4w);

    cudaFuncSetAttribute(fused_gemm_kv,
                         cudaFuncAttributeMaxDynamicSharedMemorySize, SMEM_SZ);
    dim3 grid(D_DIM / BN, M_DIM / BM);            // (8, 256)
    fused_gemm_kv<<<grid, 512, SMEM_SZ>>>(b_k, b_v);

    scanA_kernel<<<(NSEG * BD) / 256, 256>>>();
    scanB_kernel<<<BD / 128, 128>>>(h0, out_h);
    scanC_kernel<<<(NSEG * BD) / 256, 256>>>(out_o, out_h);
}